// round 5
// baseline (speedup 1.0000x reference)
#include <cuda_runtime.h>
#include <cstdint>

// GIKDWConv: depthwise 7x7 conv, stride 1, pad 3, 4-fold-rotation-symmetrized
// weights. N=16, C=384, H=W=64, fp32.
//
// R5: occupancy push #2. 512-thread blocks, each thread computes 4 rows x
// 2 cols (x 2 channels packed in f32x2). Thin per-thread tile cuts registers
// to fit 2 CTAs x 512 threads = 32 warps/SM (8/SMSP), doubling eligible-warp
// supply vs R4. Aligned LDS.128 row loads, fma.rn.f32x2 math, 13 unique
// symmetrized weights in registers.

#define HH 64
#define WW 64
#define NN 16
#define CC 384
#define TILE 70            // 64 + 2*3 halo
#define RPT 4              // output rows per thread
typedef unsigned long long ull;

// orbit id of each (ky,kx) tap under 90-degree rotation (13 unique weights)
__device__ constexpr int ORBIT[7][7] = {
    {0, 1, 2, 3, 4, 5, 0},
    {5, 6, 7, 8, 9, 6, 1},
    {4, 9,10,11,10, 7, 2},
    {3, 8,11,12,11, 8, 3},
    {2, 7,10,11,10, 9, 4},
    {1, 6, 9, 8, 7, 6, 5},
    {0, 5, 4, 3, 2, 1, 0}};
__device__ constexpr int REP_I[13] = {0,0,0,0,0,0,1,1,1,1,2,2,3};
__device__ constexpr int REP_J[13] = {0,1,2,3,4,5,1,2,3,4,2,3,3};

__device__ __forceinline__ ull fma2(ull a, ull b, ull c) {
    ull d;
    asm("fma.rn.f32x2 %0, %1, %2, %3;" : "=l"(d) : "l"(a), "l"(b), "l"(c));
    return d;
}
__device__ __forceinline__ ull pack2(float lo, float hi) {
    ull r;
    asm("mov.b64 %0, {%1, %2};" : "=l"(r) : "f"(lo), "f"(hi));
    return r;
}
__device__ __forceinline__ void unpack2(ull v, float& lo, float& hi) {
    asm("mov.b64 {%0, %1}, %2;" : "=f"(lo), "=f"(hi) : "l"(v));
}

__global__ __launch_bounds__(512, 2)
void gik_dwconv_kernel(const float* __restrict__ x,
                       const float* __restrict__ weight,
                       float* __restrict__ out) {
    __shared__ ull sx[TILE * TILE];  // packed (c0,c1) halo tile, 39.2 KB
    __shared__ ull sw[13];           // packed symmetric weights

    const int tid = threadIdx.x;
    const int cp  = blockIdx.x;        // channel pair 0..191
    const int n   = blockIdx.y;        // batch 0..15
    const int c0  = cp * 2;

    // ---- load halo tile (both channels, zero-padded) ----
    const float* x0 = x + ((n * CC + c0) * (HH * WW));
    const float* x1 = x0 + HH * WW;
    #pragma unroll 4
    for (int idx = tid; idx < TILE * TILE; idx += 512) {
        int r   = idx / TILE;
        int col = idx - r * TILE;
        int gy = r - 3, gx = col - 3;
        float v0 = 0.f, v1 = 0.f;
        if ((unsigned)gy < (unsigned)HH && (unsigned)gx < (unsigned)WW) {
            int off = gy * WW + gx;
            v0 = x0[off];
            v1 = x1[off];
        }
        sx[idx] = pack2(v0, v1);
    }

    // ---- the 13 unique symmetrized weights ----
    if (tid < 13) {
        const int i = REP_I[tid], j = REP_J[tid];
        const float* w0 = weight + c0 * 49;
        const float* w1 = w0 + 49;
        float a0 = 0.25f * (w0[i*7 + j] + w0[j*7 + (6-i)] +
                            w0[(6-i)*7 + (6-j)] + w0[(6-j)*7 + i]);
        float a1 = 0.25f * (w1[i*7 + j] + w1[j*7 + (6-i)] +
                            w1[(6-i)*7 + (6-j)] + w1[(6-j)*7 + i]);
        sw[tid] = pack2(a0, a1);
    }
    __syncthreads();

    // ---- per-thread: 4 output rows x 2 adjacent columns (x 2 channels) ----
    const int cx = (tid & 31) * 2;     // even output column 0..62
    const int r0 = (tid >> 5) * RPT;   // output row base: 0,4,...,60

    ull wreg[13];
    #pragma unroll
    for (int o = 0; o < 13; o++) wreg[o] = sw[o];

    ull acc0[RPT], acc1[RPT];          // col cx and cx+1
    #pragma unroll
    for (int r = 0; r < RPT; r++) { acc0[r] = 0ull; acc1[r] = 0ull; }

    #pragma unroll
    for (int y = 0; y < RPT + 6; y++) {
        // 8 packed inputs for this row: 4x LDS.128, aligned (cx even)
        ull xv[8];
        {
            const ulonglong2* rp = (const ulonglong2*)(sx + (r0 + y) * TILE + cx);
            #pragma unroll
            for (int q = 0; q < 4; q++) {
                ulonglong2 v = rp[q];
                xv[2*q] = v.x; xv[2*q+1] = v.y;
            }
        }
        #pragma unroll
        for (int k = 0; k < 7; k++) {
            const int r = y - k;
            if (r >= 0 && r < RPT) {
                #pragma unroll
                for (int t = 0; t < 7; t++) {
                    const ull w = wreg[ORBIT[k][t]];
                    acc0[r] = fma2(w, xv[t],     acc0[r]);
                    acc1[r] = fma2(w, xv[t + 1], acc1[r]);
                }
            }
        }
    }

    // ---- store: float2 per channel-row ----
    float* o0 = out + ((n * CC + c0) * (HH * WW));
    float* o1 = o0 + HH * WW;
    #pragma unroll
    for (int r = 0; r < RPT; r++) {
        float a, b, c, d;
        unpack2(acc0[r], a, b);   // a: c0 col cx, b: c1 col cx
        unpack2(acc1[r], c, d);   // c: c0 col cx+1, d: c1 col cx+1
        const int off = (r0 + r) * WW + cx;
        *(float2*)(o0 + off) = make_float2(a, c);
        *(float2*)(o1 + off) = make_float2(b, d);
    }
}

extern "C" void kernel_launch(void* const* d_in, const int* in_sizes, int n_in,
                              void* d_out, int out_size) {
    const float* x = (const float*)d_in[0];       // [16,384,64,64]
    const float* w = (const float*)d_in[1];       // [384,1,7,7]
    float* out = (float*)d_out;                   // [16,384,64,64]
    dim3 grid(CC / 2, NN);
    gik_dwconv_kernel<<<grid, 512>>>(x, w, out);
}

// round 6
// speedup vs baseline: 1.3615x; 1.3615x over previous
#include <cuda_runtime.h>
#include <cstdint>

// GIKDWConv: depthwise 7x7 conv, stride 1, pad 3, 4-fold-rotation-symmetrized
// weights. N=16, C=384, H=W=64, fp32.
//
// R6: cp.async software pipeline. R4's compute core (8 rows x 2 cols per
// thread, channel-pair f32x2 via fma.rn.f32x2, 13 unique weights in regs)
// on a half-height 38x70 tile, double-buffered: tile t+1 streams into smem
// via cp.async (4B ops, zfill halo) while tile t computes. 128-thread
// blocks, 5 CTAs/SM (smem-limited). Each block does both halves of one
// (n, channel-pair).

#define HH 64
#define WW 64
#define NN 16
#define CC 384
#define TR 38              // tile rows: 32 output + 6 halo
#define TC 70              // tile cols: 64 output + 6 halo
#define CELLS (TR * TC)    // 2660
#define RPT 8              // output rows per thread
typedef unsigned long long ull;

// orbit id of each (ky,kx) tap under 90-degree rotation (13 unique weights)
__device__ constexpr int ORBIT[7][7] = {
    {0, 1, 2, 3, 4, 5, 0},
    {5, 6, 7, 8, 9, 6, 1},
    {4, 9,10,11,10, 7, 2},
    {3, 8,11,12,11, 8, 3},
    {2, 7,10,11,10, 9, 4},
    {1, 6, 9, 8, 7, 6, 5},
    {0, 5, 4, 3, 2, 1, 0}};
__device__ constexpr int REP_I[13] = {0,0,0,0,0,0,1,1,1,1,2,2,3};
__device__ constexpr int REP_J[13] = {0,1,2,3,4,5,1,2,3,4,2,3,3};

__device__ __forceinline__ ull fma2(ull a, ull b, ull c) {
    ull d;
    asm("fma.rn.f32x2 %0, %1, %2, %3;" : "=l"(d) : "l"(a), "l"(b), "l"(c));
    return d;
}
__device__ __forceinline__ ull pack2(float lo, float hi) {
    ull r;
    asm("mov.b64 %0, {%1, %2};" : "=l"(r) : "f"(lo), "f"(hi));
    return r;
}
__device__ __forceinline__ void unpack2(ull v, float& lo, float& hi) {
    asm("mov.b64 {%0, %1}, %2;" : "=f"(lo), "=f"(hi) : "l"(v));
}
__device__ __forceinline__ uint32_t s2u(const void* p) {
    uint32_t a;
    asm("{ .reg .u64 t; cvta.to.shared.u64 t, %1; cvt.u32.u64 %0, t; }"
        : "=r"(a) : "l"(p));
    return a;
}
// 4-byte cp.async with zfill: sz=4 copies, sz=0 writes zeros (no src access)
__device__ __forceinline__ void cp4(uint32_t d, const float* s, int sz) {
    asm volatile("cp.async.ca.shared.global [%0], [%1], 4, %2;"
                 :: "r"(d), "l"(s), "r"(sz));
}

__global__ __launch_bounds__(128, 5)
void gik_dwconv_kernel(const float* __restrict__ x,
                       const float* __restrict__ weight,
                       float* __restrict__ out) {
    __shared__ ull sx[2 * CELLS];   // double-buffered packed half-tiles
    __shared__ ull sw[13];          // packed symmetric weights

    const int tid = threadIdx.x;
    const int cp  = blockIdx.x;         // channel pair 0..191
    const int n   = blockIdx.y;         // batch 0..15
    const int c0  = cp * 2;

    const float* x0 = x + ((n * CC + c0) * (HH * WW));
    const float* x1 = x0 + HH * WW;

    // ---- the 13 unique symmetrized weights ----
    if (tid < 13) {
        const int i = REP_I[tid], j = REP_J[tid];
        const float* w0 = weight + c0 * 49;
        const float* w1 = w0 + 49;
        float a0 = 0.25f * (w0[i*7 + j] + w0[j*7 + (6-i)] +
                            w0[(6-i)*7 + (6-j)] + w0[(6-j)*7 + i]);
        float a1 = 0.25f * (w1[i*7 + j] + w1[j*7 + (6-i)] +
                            w1[(6-i)*7 + (6-j)] + w1[(6-j)*7 + i]);
        sw[tid] = pack2(a0, a1);
    }

    const uint32_t sbase = s2u(sx);

    // ---- async tile loader: half h into buffer b ----
    auto load_tile = [&](int h, int b) {
        const int gy0 = h * 32 - 3;
        const uint32_t dst0 = sbase + (uint32_t)b * (CELLS * 8);
        #pragma unroll 3
        for (int idx = tid; idx < CELLS; idx += 128) {
            int r  = idx / TC;
            int c  = idx - r * TC;
            int gy = gy0 + r, gx = c - 3;
            int v  = ((unsigned)gy < (unsigned)HH) &
                     ((unsigned)gx < (unsigned)WW);
            int off = v ? (gy * WW + gx) : 0;
            int sz  = v ? 4 : 0;
            cp4(dst0 + idx * 8,     x0 + off, sz);
            cp4(dst0 + idx * 8 + 4, x1 + off, sz);
        }
        asm volatile("cp.async.commit_group;" ::: "memory");
    };

    load_tile(0, 0);
    __syncthreads();                    // sw visible to all

    ull wreg[13];
    #pragma unroll
    for (int o = 0; o < 13; o++) wreg[o] = sw[o];

    const int cx = (tid & 31) * 2;      // even output column 0..62
    const int r0 = (tid >> 5) * RPT;    // local output row base: 0,8,16,24

    #pragma unroll
    for (int t = 0; t < 2; t++) {       // two halves of this (n, cp)
        if (t == 0) {
            load_tile(1, 1);
            asm volatile("cp.async.wait_group 1;" ::: "memory");
        } else {
            asm volatile("cp.async.wait_group 0;" ::: "memory");
        }
        __syncthreads();

        const ull* sb = sx + t * CELLS;

        ull acc0[RPT], acc1[RPT];       // col cx and cx+1
        #pragma unroll
        for (int r = 0; r < RPT; r++) { acc0[r] = 0ull; acc1[r] = 0ull; }

        #pragma unroll
        for (int y = 0; y < RPT + 6; y++) {
            ull xv[8];                  // 8 packed inputs: 4x LDS.128
            {
                const ulonglong2* rp =
                    (const ulonglong2*)(sb + (r0 + y) * TC + cx);
                #pragma unroll
                for (int q = 0; q < 4; q++) {
                    ulonglong2 v = rp[q];
                    xv[2*q] = v.x; xv[2*q+1] = v.y;
                }
            }
            #pragma unroll
            for (int k = 0; k < 7; k++) {
                const int r = y - k;
                if (r >= 0 && r < RPT) {
                    #pragma unroll
                    for (int u = 0; u < 7; u++) {
                        const ull w = wreg[ORBIT[k][u]];
                        acc0[r] = fma2(w, xv[u],     acc0[r]);
                        acc1[r] = fma2(w, xv[u + 1], acc1[r]);
                    }
                }
            }
        }

        // ---- store: float2 per channel-row ----
        float* o0 = out + ((n * CC + c0) * (HH * WW)) + t * 32 * WW;
        float* o1 = o0 + HH * WW;
        #pragma unroll
        for (int r = 0; r < RPT; r++) {
            float a, b, c, d;
            unpack2(acc0[r], a, b);     // a: c0 col cx,   b: c1 col cx
            unpack2(acc1[r], c, d);     // c: c0 col cx+1, d: c1 col cx+1
            const int off = (r0 + r) * WW + cx;
            *(float2*)(o0 + off) = make_float2(a, c);
            *(float2*)(o1 + off) = make_float2(b, d);
        }
        __syncthreads();                // buffer t safe to reuse
    }
}

extern "C" void kernel_launch(void* const* d_in, const int* in_sizes, int n_in,
                              void* d_out, int out_size) {
    const float* x = (const float*)d_in[0];       // [16,384,64,64]
    const float* w = (const float*)d_in[1];       // [384,1,7,7]
    float* out = (float*)d_out;                   // [16,384,64,64]
    dim3 grid(CC / 2, NN);
    gik_dwconv_kernel<<<grid, 128>>>(x, w, out);
}